// round 1
// baseline (speedup 1.0000x reference)
#include <cuda_runtime.h>

// ---------------- problem constants ----------------
#define B     4
#define A     256
#define KA    256                 // atom length
#define T     16384
#define PAD   128                 // KA/2
#define TP    (T + 2*PAD)         // 16640 padded residual length
#define TOUT  (TP - KA + 1)       // 16385 conv output length
#define RPS   16896               // rp/recon stride (TP + KA, zero tail so conv tiles never OOB)
#define FMS   16896               // fm row stride = 33 chunks * 512
#define NCH   33                  // chunks per fm row
#define NITER 16

// ---------------- device scratch (no allocations allowed) ----------------
__device__ float              g_dn[A * KA];
__device__ float              g_rp[B * RPS];
__device__ float              g_recon[B * RPS];
__device__ float              g_fm[(size_t)B * A * FMS];      // ~69 MB
__device__ unsigned long long g_cmax[B * A * NCH];
__device__ int                g_sel_atom[B];
__device__ int                g_sel_pos[B];
__device__ float              g_sel_val[B];

// ---------------- helpers ----------------
__device__ __forceinline__ unsigned long long packkey(float v, unsigned flat) {
    unsigned u = __float_as_uint(v);
    u = (u & 0x80000000u) ? ~u : (u | 0x80000000u);   // orderable float
    // low 32 bits = ~flat so ties prefer the SMALLEST flat index (matches jnp.argmax)
    return ((unsigned long long)u << 32) | (unsigned)(~flat);
}

// ---------------- kernels ----------------

// normalize each atom over its 256 samples: dn = d / (||d|| + 1e-12)
__global__ void normd_kernel(const float* __restrict__ d) {
    const int a = blockIdx.x;
    const float v = d[a * KA + threadIdx.x];
    float ss = v * v;
    #pragma unroll
    for (int o = 16; o; o >>= 1) ss += __shfl_down_sync(0xffffffffu, ss, o);
    __shared__ float s[8];
    __shared__ float norm;
    if ((threadIdx.x & 31) == 0) s[threadIdx.x >> 5] = ss;
    __syncthreads();
    if (threadIdx.x == 0) {
        float tot = 0.f;
        #pragma unroll
        for (int i = 0; i < 8; i++) tot += s[i];
        norm = sqrtf(tot) + 1e-12f;
    }
    __syncthreads();
    g_dn[a * KA + threadIdx.x] = v / norm;
}

// zero rp/recon (incl. tail padding), copy x into padded residual
__global__ void init_kernel(const float* __restrict__ x) {
    const int idx = blockIdx.x * blockDim.x + threadIdx.x;
    if (idx >= B * RPS) return;
    const int b = idx / RPS, t = idx - b * RPS;
    float v = 0.f;
    if (t >= PAD && t < PAD + T) v = x[b * T + (t - PAD)];
    g_rp[idx] = v;
    g_recon[idx] = 0.f;
}

// conv: fm[b,a,t] = sum_k rp[b,t+k] * dn[a,k]
// tile: 64 t x 64 a, 256 threads (16 t-threads x 16 a-threads), 4x4 regs/thread
template <bool WINDOW>
__global__ void __launch_bounds__(256) conv_kernel() {
    const int b = blockIdx.z;
    int tbase, tlim;
    if (WINDOW) {
        const int pos = g_sel_pos[b];
        const int lo = max(0, pos - (KA - 1));
        tlim = min(TOUT, pos + KA);               // exclusive
        tbase = lo + blockIdx.x * 64;
        if (tbase >= tlim) return;
    } else {
        tbase = blockIdx.x * 64;
        tlim = TOUT;
    }
    const int a0 = blockIdx.y * 64;
    const int tid = threadIdx.x;
    const int tt = tid & 15;
    const int ta = tid >> 4;
    const float* __restrict__ rp = g_rp + b * RPS;

    __shared__ float s_rp[96];
    __shared__ float s_dn[32][65];

    float acc[4][4];
    #pragma unroll
    for (int i = 0; i < 4; i++)
        #pragma unroll
        for (int j = 0; j < 4; j++) acc[i][j] = 0.f;

    for (int kc = 0; kc < KA; kc += 32) {
        __syncthreads();
        if (tid < 96) s_rp[tid] = rp[tbase + kc + tid];
        #pragma unroll
        for (int l = 0; l < 8; l++) {
            const int i  = tid + l * 256;
            const int aa = i >> 5;
            const int kk = i & 31;
            s_dn[kk][aa] = g_dn[(a0 + aa) * KA + kc + kk];
        }
        __syncthreads();
        #pragma unroll
        for (int kk = 0; kk < 32; kk++) {
            const float r0 = s_rp[tt + kk];
            const float r1 = s_rp[tt + 16 + kk];
            const float r2 = s_rp[tt + 32 + kk];
            const float r3 = s_rp[tt + 48 + kk];
            const float d0 = s_dn[kk][ta];
            const float d1 = s_dn[kk][ta + 16];
            const float d2 = s_dn[kk][ta + 32];
            const float d3 = s_dn[kk][ta + 48];
            acc[0][0] += r0 * d0; acc[0][1] += r0 * d1; acc[0][2] += r0 * d2; acc[0][3] += r0 * d3;
            acc[1][0] += r1 * d0; acc[1][1] += r1 * d1; acc[1][2] += r1 * d2; acc[1][3] += r1 * d3;
            acc[2][0] += r2 * d0; acc[2][1] += r2 * d1; acc[2][2] += r2 * d2; acc[2][3] += r2 * d3;
            acc[3][0] += r3 * d0; acc[3][1] += r3 * d1; acc[3][2] += r3 * d2; acc[3][3] += r3 * d3;
        }
    }
    #pragma unroll
    for (int j = 0; j < 4; j++) {
        const int a = a0 + ta + 16 * j;
        float* __restrict__ row = g_fm + (size_t)(b * A + a) * FMS;
        #pragma unroll
        for (int i = 0; i < 4; i++) {
            const int t = tbase + tt + 16 * i;
            if (t < tlim) row[t] = acc[i][j];
        }
    }
}

// recompute chunk maxima. full: all 33 chunks. window: <=2 chunks touching the update.
template <bool WINDOW>
__global__ void __launch_bounds__(128) chunkmax_kernel() {
    const int b = blockIdx.z, a = blockIdx.y;
    int c;
    if (WINDOW) {
        const int pos = g_sel_pos[b];
        const int lo = max(0, pos - (KA - 1));
        const int hi = min(TOUT - 1, pos + (KA - 1));
        c = (lo >> 9) + blockIdx.x;
        if (c > (hi >> 9)) return;
    } else {
        c = blockIdx.x;
    }
    const int t0 = c << 9;
    const int t1 = min(t0 + 512, TOUT);
    const float* __restrict__ row = g_fm + (size_t)(b * A + a) * FMS;
    unsigned long long best = 0ull;
    for (int t = t0 + threadIdx.x; t < t1; t += 128) {
        const unsigned long long k = packkey(row[t], (unsigned)(a * TOUT + t));
        if (k > best) best = k;
    }
    #pragma unroll
    for (int o = 16; o; o >>= 1) {
        const unsigned long long x = __shfl_down_sync(0xffffffffu, best, o);
        if (x > best) best = x;
    }
    __shared__ unsigned long long s[4];
    if ((threadIdx.x & 31) == 0) s[threadIdx.x >> 5] = best;
    __syncthreads();
    if (threadIdx.x == 0) {
        best = s[0];
        #pragma unroll
        for (int w = 1; w < 4; w++) if (s[w] > best) best = s[w];
        g_cmax[(b * A + a) * NCH + c] = best;
    }
}

// per-batch argmax over all (a, chunk) packed maxima; decode atom/pos/val exactly
__global__ void __launch_bounds__(256) argmax_kernel() {
    const int b = blockIdx.x;
    const unsigned long long* __restrict__ cm = g_cmax + b * A * NCH;
    unsigned long long best = 0ull;
    for (int i = threadIdx.x; i < A * NCH; i += 256) {
        const unsigned long long k = cm[i];
        if (k > best) best = k;
    }
    #pragma unroll
    for (int o = 16; o; o >>= 1) {
        const unsigned long long x = __shfl_down_sync(0xffffffffu, best, o);
        if (x > best) best = x;
    }
    __shared__ unsigned long long s[8];
    if ((threadIdx.x & 31) == 0) s[threadIdx.x >> 5] = best;
    __syncthreads();
    if (threadIdx.x == 0) {
        best = s[0];
        #pragma unroll
        for (int w = 1; w < 8; w++) if (s[w] > best) best = s[w];
        const unsigned hiw = (unsigned)(best >> 32);
        const unsigned u = (hiw & 0x80000000u) ? (hiw & 0x7fffffffu) : ~hiw;
        const unsigned flat = ~(unsigned)(best & 0xffffffffu);
        g_sel_atom[b] = flat / TOUT;
        g_sel_pos[b]  = flat % TOUT;
        g_sel_val[b]  = __uint_as_float(u);
    }
}

// rp[p..p+K) -= val*dn[sel];  recon[p..p+K) += val*dn[sel]
__global__ void update_kernel() {
    const int b = blockIdx.x;
    const int k = threadIdx.x;
    const int a = g_sel_atom[b];
    const int p = g_sel_pos[b];
    const float v = g_sel_val[b];
    const float x = v * g_dn[a * KA + k];
    g_rp[b * RPS + p + k]    -= x;
    g_recon[b * RPS + p + k] += x;
}

// crop padded recon to output
__global__ void out_kernel(float* __restrict__ out) {
    const int idx = blockIdx.x * blockDim.x + threadIdx.x;
    if (idx >= B * T) return;
    const int b = idx / T, t = idx - b * T;
    out[idx] = g_recon[b * RPS + PAD + t];
}

// ---------------- launch ----------------
extern "C" void kernel_launch(void* const* d_in, const int* in_sizes, int n_in,
                              void* d_out, int out_size) {
    const float* x = (const float*)d_in[0];
    const float* d = (const float*)d_in[1];
    float* out = (float*)d_out;
    (void)in_sizes; (void)n_in; (void)out_size;

    normd_kernel<<<A, KA>>>(d);
    init_kernel<<<(B * RPS + 255) / 256, 256>>>(x);

    // full correlation: t-tiles=257, a-tiles=4, batches=4
    conv_kernel<false><<<dim3(257, 4, B), 256>>>();
    chunkmax_kernel<false><<<dim3(NCH, A, B), 128>>>();

    for (int it = 0; it < NITER; ++it) {
        argmax_kernel<<<B, 256>>>();
        update_kernel<<<B, KA>>>();
        if (it < NITER - 1) {
            // window: <=511 positions -> 8 t-tiles of 64
            conv_kernel<true><<<dim3(8, 4, B), 256>>>();
            chunkmax_kernel<true><<<dim3(2, A, B), 128>>>();
        }
    }
    out_kernel<<<(B * T + 255) / 256, 256>>>(out);
}

// round 2
// speedup vs baseline: 1.0279x; 1.0279x over previous
#include <cuda_runtime.h>

// ---------------- problem constants ----------------
#define B     4
#define A     256
#define KA    256                 // atom length
#define T     16384
#define PAD   128                 // KA/2
#define TP    (T + 2*PAD)         // 16640 padded residual length
#define TOUT  (TP - KA + 1)       // 16385 conv output length
#define RPS   16896               // rp/recon stride (zero tail so conv tiles never OOB)
#define FMS   16896               // fm row stride = 33 chunks * 512
#define NCH   33                  // 512-wide chunks per fm row
#define NITER 16

// ---------------- device scratch ----------------
__device__ float              g_dn[A * KA];
__device__ float              g_rp[B * RPS];
__device__ float              g_recon[B * RPS];
__device__ float              g_fm[(size_t)B * A * FMS];      // ~69 MB
__device__ unsigned long long g_cmax[B * A * NCH];
__device__ int                g_sel_atom[B];
__device__ int                g_sel_pos[B];
__device__ float              g_sel_val[B];

// ---------------- helpers ----------------
__device__ __forceinline__ unsigned long long packkey(float v, unsigned flat) {
    unsigned u = __float_as_uint(v);
    u = (u & 0x80000000u) ? ~u : (u | 0x80000000u);   // orderable float
    return ((unsigned long long)u << 32) | (unsigned)(~flat);  // ties -> smallest flat
}
__device__ __forceinline__ unsigned long long pack2(float lo, float hi) {
    unsigned long long r;
    asm("mov.b64 %0, {%1, %2};" : "=l"(r) : "f"(lo), "f"(hi));
    return r;
}
__device__ __forceinline__ void unpack2(unsigned long long v, float& lo, float& hi) {
    asm("mov.b64 {%0, %1}, %2;" : "=f"(lo), "=f"(hi) : "l"(v));
}
__device__ __forceinline__ void ffma2(unsigned long long& acc,
                                      unsigned long long a, unsigned long long b) {
    asm("fma.rn.f32x2 %0, %1, %2, %0;" : "+l"(acc) : "l"(a), "l"(b));
}

// ---------------- kernels ----------------

// normalize each atom: dn = d / (||d|| + 1e-12)
__global__ void normd_kernel(const float* __restrict__ d) {
    const int a = blockIdx.x;
    const float v = d[a * KA + threadIdx.x];
    float ss = v * v;
    #pragma unroll
    for (int o = 16; o; o >>= 1) ss += __shfl_down_sync(0xffffffffu, ss, o);
    __shared__ float s[8];
    __shared__ float norm;
    if ((threadIdx.x & 31) == 0) s[threadIdx.x >> 5] = ss;
    __syncthreads();
    if (threadIdx.x == 0) {
        float tot = 0.f;
        #pragma unroll
        for (int i = 0; i < 8; i++) tot += s[i];
        norm = sqrtf(tot) + 1e-12f;
    }
    __syncthreads();
    g_dn[a * KA + threadIdx.x] = v / norm;
}

// zero rp/recon/cmax, copy x into padded residual
__global__ void init_kernel(const float* __restrict__ x) {
    const int idx = blockIdx.x * blockDim.x + threadIdx.x;
    if (idx < B * A * NCH) g_cmax[idx] = 0ull;
    if (idx >= B * RPS) return;
    const int b = idx / RPS, t = idx - b * RPS;
    float v = 0.f;
    if (t >= PAD && t < PAD + T) v = x[b * T + (t - PAD)];
    g_rp[idx] = v;
    g_recon[idx] = 0.f;
}

// conv: fm[b,a,t] = sum_k rp[b,t+k] * dn[a,k]
// tile: 64 t x 64 a, 256 threads = (16 tt) x (16 ta); per thread 4 t x 4 a
// FFMA2 packed math: atoms in adjacent pairs (2*ta, 2*ta+1) and (2*ta+32, 2*ta+33)
// Full mode also folds chunk-max (atomicMax on packed keys) into the epilogue.
template <bool WINDOW>
__global__ void __launch_bounds__(256) conv_kernel() {
    const int b = blockIdx.z;
    int tbase, tlim;
    if (WINDOW) {
        const int pos = g_sel_pos[b];
        const int lo = max(0, pos - (KA - 1));
        tlim = min(TOUT, pos + KA);               // exclusive
        tbase = lo + blockIdx.x * 64;
        if (tbase >= tlim) return;
    } else {
        tbase = blockIdx.x * 64;
        tlim = TOUT;
    }
    const int a0 = blockIdx.y * 64;
    const int tid = threadIdx.x;
    const int tt = tid & 15;
    const int ta = tid >> 4;
    const float* __restrict__ rp = g_rp + b * RPS;

    __shared__ unsigned long long s_rp2[96];   // (r, r) duplicated pairs
    __shared__ float s_dn[32][66];             // [k][atom], 8B-aligned pair reads

    unsigned long long acc2[4][2];
    #pragma unroll
    for (int i = 0; i < 4; i++) { acc2[i][0] = 0ull; acc2[i][1] = 0ull; }

    for (int kc = 0; kc < KA; kc += 32) {
        __syncthreads();
        if (tid < 96) {
            const float r = rp[tbase + kc + tid];
            s_rp2[tid] = pack2(r, r);
        }
        #pragma unroll
        for (int l = 0; l < 8; l++) {
            const int i  = tid + l * 256;
            const int aa = i >> 5;
            const int kk = i & 31;
            s_dn[kk][aa] = g_dn[(a0 + aa) * KA + kc + kk];
        }
        __syncthreads();
        #pragma unroll
        for (int kk = 0; kk < 32; kk++) {
            const unsigned long long dp0 =
                *reinterpret_cast<const unsigned long long*>(&s_dn[kk][2 * ta]);
            const unsigned long long dp1 =
                *reinterpret_cast<const unsigned long long*>(&s_dn[kk][2 * ta + 32]);
            const unsigned long long r0 = s_rp2[tt + kk];
            const unsigned long long r1 = s_rp2[tt + 16 + kk];
            const unsigned long long r2 = s_rp2[tt + 32 + kk];
            const unsigned long long r3 = s_rp2[tt + 48 + kk];
            ffma2(acc2[0][0], r0, dp0); ffma2(acc2[0][1], r0, dp1);
            ffma2(acc2[1][0], r1, dp0); ffma2(acc2[1][1], r1, dp1);
            ffma2(acc2[2][0], r2, dp0); ffma2(acc2[2][1], r2, dp1);
            ffma2(acc2[3][0], r3, dp0); ffma2(acc2[3][1], r3, dp1);
        }
    }

    // unpack: vals[i][u] for atom index u in {pair0.lo, pair0.hi, pair1.lo, pair1.hi}
    float vals[4][4];
    #pragma unroll
    for (int i = 0; i < 4; i++) {
        unpack2(acc2[i][0], vals[i][0], vals[i][1]);
        unpack2(acc2[i][1], vals[i][2], vals[i][3]);
    }

    // store to fm
    #pragma unroll
    for (int u = 0; u < 4; u++) {
        const int a = a0 + 2 * ta + (u & 1) + 32 * (u >> 1);
        float* __restrict__ row = g_fm + (size_t)(b * A + a) * FMS;
        #pragma unroll
        for (int i = 0; i < 4; i++) {
            const int t = tbase + tt + 16 * i;
            if (t < tlim) row[t] = vals[i][u];
        }
    }

    if (!WINDOW) {
        // fused chunk-max: tbase is 64-aligned -> whole tile in one 512-chunk
        const int c = tbase >> 9;
        #pragma unroll
        for (int u = 0; u < 4; u++) {
            const int a = a0 + 2 * ta + (u & 1) + 32 * (u >> 1);
            unsigned long long best = 0ull;
            #pragma unroll
            for (int i = 0; i < 4; i++) {
                const int t = tbase + tt + 16 * i;
                if (t < tlim) {
                    const unsigned long long k =
                        packkey(vals[i][u], (unsigned)(a * TOUT + t));
                    if (k > best) best = k;
                }
            }
            #pragma unroll
            for (int o = 8; o; o >>= 1) {
                const unsigned long long x = __shfl_down_sync(0xffffffffu, best, o, 16);
                if (x > best) best = x;
            }
            if (tt == 0)
                atomicMax(&g_cmax[(b * A + a) * NCH + c], best);
        }
    }
}

// window chunk-max rebuild: <=2 chunks touching the update, full 512-wide rescan
__global__ void __launch_bounds__(128) chunkmax_w_kernel() {
    const int b = blockIdx.z, a = blockIdx.y;
    const int pos = g_sel_pos[b];
    const int lo = max(0, pos - (KA - 1));
    const int hi = min(TOUT - 1, pos + (KA - 1));
    const int c = (lo >> 9) + blockIdx.x;
    if (c > (hi >> 9)) return;
    const int t0 = c << 9;
    const int t1 = min(t0 + 512, TOUT);
    const float* __restrict__ row = g_fm + (size_t)(b * A + a) * FMS;
    unsigned long long best = 0ull;
    for (int t = t0 + threadIdx.x; t < t1; t += 128) {
        const unsigned long long k = packkey(row[t], (unsigned)(a * TOUT + t));
        if (k > best) best = k;
    }
    #pragma unroll
    for (int o = 16; o; o >>= 1) {
        const unsigned long long x = __shfl_down_sync(0xffffffffu, best, o);
        if (x > best) best = x;
    }
    __shared__ unsigned long long s[4];
    if ((threadIdx.x & 31) == 0) s[threadIdx.x >> 5] = best;
    __syncthreads();
    if (threadIdx.x == 0) {
        best = s[0];
        #pragma unroll
        for (int w = 1; w < 4; w++) if (s[w] > best) best = s[w];
        g_cmax[(b * A + a) * NCH + c] = best;
    }
}

// fused per-batch argmax + residual/recon update (one block per batch)
__global__ void __launch_bounds__(256) argmax_update_kernel() {
    const int b = blockIdx.x;
    const unsigned long long* __restrict__ cm = g_cmax + b * A * NCH;
    unsigned long long best = 0ull;
    for (int i = threadIdx.x; i < A * NCH; i += 256) {
        const unsigned long long k = cm[i];
        if (k > best) best = k;
    }
    #pragma unroll
    for (int o = 16; o; o >>= 1) {
        const unsigned long long x = __shfl_down_sync(0xffffffffu, best, o);
        if (x > best) best = x;
    }
    __shared__ unsigned long long s[8];
    __shared__ int sh_a, sh_p;
    __shared__ float sh_v;
    if ((threadIdx.x & 31) == 0) s[threadIdx.x >> 5] = best;
    __syncthreads();
    if (threadIdx.x == 0) {
        best = s[0];
        #pragma unroll
        for (int w = 1; w < 8; w++) if (s[w] > best) best = s[w];
        const unsigned hiw = (unsigned)(best >> 32);
        const unsigned u = (hiw & 0x80000000u) ? (hiw & 0x7fffffffu) : ~hiw;
        const unsigned flat = ~(unsigned)(best & 0xffffffffu);
        sh_a = flat / TOUT;
        sh_p = flat % TOUT;
        sh_v = __uint_as_float(u);
        g_sel_atom[b] = sh_a;
        g_sel_pos[b]  = sh_p;
        g_sel_val[b]  = sh_v;
    }
    __syncthreads();
    // update: rp -= val*dn[sel], recon += val*dn[sel] (256 threads == KA)
    const int k = threadIdx.x;
    const float x = sh_v * g_dn[sh_a * KA + k];
    g_rp[b * RPS + sh_p + k]    -= x;
    g_recon[b * RPS + sh_p + k] += x;
}

// crop padded recon to output
__global__ void out_kernel(float* __restrict__ out) {
    const int idx = blockIdx.x * blockDim.x + threadIdx.x;
    if (idx >= B * T) return;
    const int b = idx / T, t = idx - b * T;
    out[idx] = g_recon[b * RPS + PAD + t];
}

// ---------------- launch ----------------
extern "C" void kernel_launch(void* const* d_in, const int* in_sizes, int n_in,
                              void* d_out, int out_size) {
    const float* x = (const float*)d_in[0];
    const float* d = (const float*)d_in[1];
    float* out = (float*)d_out;
    (void)in_sizes; (void)n_in; (void)out_size;

    normd_kernel<<<A, KA>>>(d);
    init_kernel<<<(B * RPS + 255) / 256, 256>>>(x);

    // full correlation (chunk-max fused via atomics)
    conv_kernel<false><<<dim3(257, 4, B), 256>>>();

    for (int it = 0; it < NITER; ++it) {
        argmax_update_kernel<<<B, 256>>>();
        if (it < NITER - 1) {
            conv_kernel<true><<<dim3(8, 4, B), 256>>>();   // <=511 positions
            chunkmax_w_kernel<<<dim3(2, A, B), 128>>>();
        }
    }
    out_kernel<<<(B * T + 255) / 256, 256>>>(out);
}

// round 3
// speedup vs baseline: 1.2165x; 1.1835x over previous
#include <cuda_runtime.h>

typedef unsigned long long u64;

// ---------------- problem constants ----------------
#define B     4
#define A     256
#define KA    256                 // atom length
#define T     16384
#define PAD   128                 // KA/2
#define TOUT  16385               // conv output length (T + 2*PAD - KA + 1)
#define RPS   16960               // rp/recon stride, zero tail so all tile loads stay in-bounds
#define FMS   16896               // fm row stride = 33 chunks * 512
#define NCH   33                  // 512-wide chunks per fm row
#define NITER 16

#define SWZ(j) ((j) + ((j) >> 4))   // bank-conflict swizzle for window rp smem

// ---------------- device scratch ----------------
__device__ float g_dn[A * KA];
__device__ float g_rp[B * RPS];
__device__ float g_recon[B * RPS];
__device__ float g_fm[(size_t)B * A * FMS];
__device__ u64   g_cmax[B * A * NCH];
__device__ u64   g_gbest[B];
__device__ int   g_sel_pos[B];

// ---------------- helpers ----------------
__device__ __forceinline__ u64 packkey(float v, unsigned flat) {
    unsigned u = __float_as_uint(v);
    u = (u & 0x80000000u) ? ~u : (u | 0x80000000u);     // orderable float
    return ((u64)u << 32) | (unsigned)(~flat);          // ties -> smallest flat
}
__device__ __forceinline__ u64 pack2(float lo, float hi) {
    u64 r;
    asm("mov.b64 %0, {%1, %2};" : "=l"(r) : "f"(lo), "f"(hi));
    return r;
}
__device__ __forceinline__ void unpack2(u64 v, float& lo, float& hi) {
    asm("mov.b64 {%0, %1}, %2;" : "=f"(lo), "=f"(hi) : "l"(v));
}
__device__ __forceinline__ void ffma2(u64& acc, u64 a, u64 b) {
    asm("fma.rn.f32x2 %0, %1, %2, %0;" : "+l"(acc) : "l"(a), "l"(b));
}
__device__ __forceinline__ u64 umax(u64 a, u64 b) { return a > b ? a : b; }

// ---------------- setup kernels ----------------
__global__ void normd_kernel(const float* __restrict__ d) {
    const int a = blockIdx.x;
    const float v = d[a * KA + threadIdx.x];
    float ss = v * v;
    #pragma unroll
    for (int o = 16; o; o >>= 1) ss += __shfl_down_sync(0xffffffffu, ss, o);
    __shared__ float s[8];
    __shared__ float norm;
    if ((threadIdx.x & 31) == 0) s[threadIdx.x >> 5] = ss;
    __syncthreads();
    if (threadIdx.x == 0) {
        float tot = 0.f;
        #pragma unroll
        for (int i = 0; i < 8; i++) tot += s[i];
        norm = sqrtf(tot) + 1e-12f;
    }
    __syncthreads();
    g_dn[a * KA + threadIdx.x] = v / norm;
}

__global__ void init_kernel(const float* __restrict__ x) {
    const int idx = blockIdx.x * blockDim.x + threadIdx.x;
    if (idx < B) g_gbest[idx] = 0ull;
    if (idx < B * A * NCH) g_cmax[idx] = 0ull;
    if (idx >= B * RPS) return;
    const int b = idx / RPS, t = idx - b * RPS;
    float v = 0.f;
    if (t >= PAD && t < PAD + T) v = x[b * T + (t - PAD)];
    g_rp[idx] = v;
    g_recon[idx] = 0.f;
}

// ---------------- full correlation ----------------
// block: 256 thr = 8 warps. warp w -> t range [tbase + 16w, +16); lane l -> atom pair (a0+2l, a0+2l+1).
// rp slides through a 16-slot register ring refilled by broadcast LDS (8B/warp/k);
// dn pair read as one LDS.64 (256B/warp/k). 16 FFMA2 : 2 LDS per k -> fma-pipe bound.
__global__ void __launch_bounds__(256) conv_full_kernel() {
    const int b = blockIdx.z;
    const int tbase = blockIdx.x * 128;
    const int a0 = blockIdx.y * 64;
    const int tid = threadIdx.x;
    const int w = tid >> 5, l = tid & 31;

    __shared__ float s_dnf[128][66];
    __shared__ u64   s_rp2[384];
    __shared__ u64   s_red[64];

    const float* __restrict__ rp = g_rp + b * RPS;

    if (tid < 64) s_red[tid] = 0ull;
    for (int j = tid; j < 384; j += 256) {
        const float r = rp[tbase + j];
        s_rp2[j] = pack2(r, r);
    }

    u64 acc2[16], rbuf[16];
    #pragma unroll
    for (int i = 0; i < 16; i++) acc2[i] = 0ull;

    const int tw = w * 16;

    #pragma unroll 1
    for (int kc = 0; kc < 256; kc += 128) {
        // stage dictionary k-chunk: [k][atom] with pad-66 rows
        __syncthreads();
        for (int i = tid; i < 64 * 128; i += 256) {
            const int k = i & 127, aa = i >> 7;
            s_dnf[k][aa] = g_dn[(a0 + aa) * KA + kc + k];
        }
        __syncthreads();
        if (kc == 0) {
            #pragma unroll
            for (int j = 0; j < 16; j++) rbuf[j] = s_rp2[tw + j];
        }
        #pragma unroll 1
        for (int k8 = 0; k8 < 128; k8 += 16) {
            #pragma unroll
            for (int kk = 0; kk < 16; kk++) {
                const u64 dp = *reinterpret_cast<const u64*>(&s_dnf[k8 + kk][2 * l]);
                #pragma unroll
                for (int i = 0; i < 16; i++)
                    ffma2(acc2[i], rbuf[(i + kk) & 15], dp);
                rbuf[kk] = s_rp2[tw + kc + k8 + kk + 16];
            }
        }
    }

    float vlo[16], vhi[16];
    #pragma unroll
    for (int i = 0; i < 16; i++) unpack2(acc2[i], vlo[i], vhi[i]);

    const int alo = a0 + 2 * l;
    float* __restrict__ rowlo = g_fm + (size_t)(b * A + alo) * FMS;
    float* __restrict__ rowhi = rowlo + FMS;
    const int t0 = tbase + tw;

    if (tbase + 128 <= TOUT) {
        #pragma unroll
        for (int q = 0; q < 4; q++) {
            float4 wl = make_float4(vlo[4*q], vlo[4*q+1], vlo[4*q+2], vlo[4*q+3]);
            float4 wh = make_float4(vhi[4*q], vhi[4*q+1], vhi[4*q+2], vhi[4*q+3]);
            *reinterpret_cast<float4*>(&rowlo[t0 + 4*q]) = wl;
            *reinterpret_cast<float4*>(&rowhi[t0 + 4*q]) = wh;
        }
    } else {
        #pragma unroll
        for (int i = 0; i < 16; i++) {
            const int t = t0 + i;
            if (t < TOUT) { rowlo[t] = vlo[i]; rowhi[t] = vhi[i]; }
        }
    }

    // fused chunk-max: 128-t block sits inside one 512-chunk
    u64 klo = 0ull, khi = 0ull;
    #pragma unroll
    for (int i = 0; i < 16; i++) {
        const int t = t0 + i;
        if (t < TOUT) {
            klo = umax(klo, packkey(vlo[i], (unsigned)(alo * TOUT + t)));
            khi = umax(khi, packkey(vhi[i], (unsigned)((alo + 1) * TOUT + t)));
        }
    }
    atomicMax(&s_red[2 * l],     klo);
    atomicMax(&s_red[2 * l + 1], khi);
    __syncthreads();
    if (tid < 64) {
        const int c = tbase >> 9;
        atomicMax(&g_cmax[(b * A + a0 + tid) * NCH + c], s_red[tid]);
    }
}

// initial atom-max + global best after full conv
__global__ void atommax_kernel() {
    const int a = blockIdx.x, b = blockIdx.y, l = threadIdx.x;
    const u64* __restrict__ cm = g_cmax + (b * A + a) * NCH;
    u64 v = cm[l];
    if (l == 0) v = umax(v, cm[32]);
    #pragma unroll
    for (int o = 16; o; o >>= 1) v = umax(v, __shfl_xor_sync(0xffffffffu, v, o));
    if (l == 0) atomicMax(&g_gbest[b], v);
}

// ---------------- per-iteration kernels ----------------
// K1: decode global best, update rp/recon, publish pos, reset g_gbest
__global__ void select_update_kernel() {
    const int b = blockIdx.x;
    __shared__ int sa, sp;
    __shared__ float sv;
    if (threadIdx.x == 0) {
        const u64 best = g_gbest[b];
        const unsigned hiw = (unsigned)(best >> 32);
        const unsigned u = (hiw & 0x80000000u) ? (hiw & 0x7fffffffu) : ~hiw;
        const unsigned flat = ~(unsigned)(best & 0xffffffffu);
        sa = flat / TOUT;
        sp = flat % TOUT;
        sv = __uint_as_float(u);
        g_sel_pos[b] = sp;
        g_gbest[b] = 0ull;
    }
    __syncthreads();
    const int k = threadIdx.x;
    const float x = sv * g_dn[sa * KA + k];
    g_rp[b * RPS + sp + k]    -= x;
    g_recon[b * RPS + sp + k] += x;
}

// K2: window re-correlation (<=511 positions, 8 atoms/block) fused with
// chunk rebuild, atom max, and atomicMax into g_gbest.
__global__ void __launch_bounds__(256) conv_win_kernel() {
    const int b = blockIdx.y;
    const int a0 = blockIdx.x * 8;
    const int pos = g_sel_pos[b];
    const int lo = max(0, pos - (KA - 1));
    const int hi = min(TOUT - 1, pos + (KA - 1));
    const int tid = threadIdx.x;

    __shared__ u64 s_rp2[832];        // swizzled (r,r) pairs
    __shared__ u64 s_dn2[256 * 4];    // [k][pair]

    const float* __restrict__ rp = g_rp + b * RPS;
    for (int j = tid; j < 776; j += 256) {
        const float r = rp[lo + j];                  // zero tail keeps this in-bounds
        s_rp2[SWZ(j)] = pack2(r, r);
    }
    for (int i = tid; i < 1024; i += 256) {
        const int k = i & 255, p = i >> 8;
        s_dn2[k * 4 + p] = pack2(g_dn[(a0 + 2 * p) * KA + k],
                                 g_dn[(a0 + 2 * p + 1) * KA + k]);
    }
    __syncthreads();

    const int w = tid >> 5, l = tid & 31;
    const int p = w & 3, h = w >> 2;
    const int t0 = h * 256 + l * 8;

    u64 acc2[8], rbuf[8];
    #pragma unroll
    for (int i = 0; i < 8; i++) acc2[i] = 0ull;
    #pragma unroll
    for (int j = 0; j < 8; j++) rbuf[j] = s_rp2[SWZ(t0 + j)];

    #pragma unroll 1
    for (int k8 = 0; k8 < 256; k8 += 8) {
        #pragma unroll
        for (int kk = 0; kk < 8; kk++) {
            const u64 dp = s_dn2[(k8 + kk) * 4 + p];
            #pragma unroll
            for (int i = 0; i < 8; i++)
                ffma2(acc2[i], rbuf[(i + kk) & 7], dp);
            rbuf[kk] = s_rp2[SWZ(t0 + k8 + kk + 8)];
        }
    }

    float vlo[8], vhi[8];
    #pragma unroll
    for (int i = 0; i < 8; i++) unpack2(acc2[i], vlo[i], vhi[i]);

    const int alo = a0 + 2 * p;
    float* __restrict__ rowlo = g_fm + (size_t)(b * A + alo) * FMS;
    float* __restrict__ rowhi = rowlo + FMS;
    #pragma unroll
    for (int i = 0; i < 8; i++) {
        const int t = lo + t0 + i;
        if (t <= hi) { rowlo[t] = vlo[i]; rowhi[t] = vhi[i]; }
    }
    __syncthreads();   // make fm writes visible to the whole block

    // rebuild: warp w owns atom a0 + w; scan its 1-2 touched chunks
    const int aw = a0 + w;
    const int c0 = lo >> 9, c1 = hi >> 9;
    const int tstart = c0 << 9;
    const int tend = min((c1 + 1) << 9, TOUT);
    const float* __restrict__ rowa = g_fm + (size_t)(b * A + aw) * FMS;

    u64 b0 = 0ull, b1 = 0ull;
    for (int t = tstart + l; t < tend; t += 32) {
        const u64 key = packkey(rowa[t], (unsigned)(aw * TOUT + t));
        if ((t >> 9) == c0) b0 = umax(b0, key); else b1 = umax(b1, key);
    }
    #pragma unroll
    for (int o = 16; o; o >>= 1) {
        b0 = umax(b0, __shfl_xor_sync(0xffffffffu, b0, o));
        b1 = umax(b1, __shfl_xor_sync(0xffffffffu, b1, o));
    }
    u64* cmrow = g_cmax + (b * A + aw) * NCH;
    if (l == 0) {
        cmrow[c0] = b0;
        if (c1 != c0) cmrow[c1] = b1;
    }
    // atom max over all 33 chunks (use register values for rebuilt ones)
    u64 v = (l == c0) ? b0 : ((l == c1) ? b1 : cmrow[l]);
    if (l == 0) {
        const u64 v2 = (32 == c0) ? b0 : ((32 == c1) ? b1 : cmrow[32]);
        v = umax(v, v2);
    }
    #pragma unroll
    for (int o = 16; o; o >>= 1) v = umax(v, __shfl_xor_sync(0xffffffffu, v, o));
    if (l == 0) atomicMax(&g_gbest[b], v);
}

// crop padded recon to output
__global__ void out_kernel(float* __restrict__ out) {
    const int idx = blockIdx.x * blockDim.x + threadIdx.x;
    if (idx >= B * T) return;
    const int b = idx / T, t = idx - b * T;
    out[idx] = g_recon[b * RPS + PAD + t];
}

// ---------------- launch ----------------
extern "C" void kernel_launch(void* const* d_in, const int* in_sizes, int n_in,
                              void* d_out, int out_size) {
    const float* x = (const float*)d_in[0];
    const float* d = (const float*)d_in[1];
    float* out = (float*)d_out;
    (void)in_sizes; (void)n_in; (void)out_size;

    normd_kernel<<<A, KA>>>(d);
    init_kernel<<<(B * RPS + 255) / 256, 256>>>(x);

    conv_full_kernel<<<dim3(129, 4, B), 256>>>();
    atommax_kernel<<<dim3(A, B), 32>>>();

    for (int it = 0; it < NITER; ++it) {
        select_update_kernel<<<B, KA>>>();
        if (it < NITER - 1)
            conv_win_kernel<<<dim3(32, B), 256>>>();
    }
    out_kernel<<<(B * T + 255) / 256, 256>>>(out);
}

// round 4
// speedup vs baseline: 1.2172x; 1.0005x over previous
#include <cuda_runtime.h>

typedef unsigned long long u64;

// ---------------- problem constants ----------------
#define B     4
#define A     256
#define KA    256                 // atom length
#define T     16384
#define PAD   128                 // KA/2
#define TOUT  16385               // conv output length (T + 2*PAD - KA + 1)
#define RPS   16960               // rp/recon stride, zero tail so all tile loads stay in-bounds
#define FMS   16896               // fm row stride = 33 chunks * 512
#define NCH   33                  // 512-wide chunks per fm row
#define NITER 16
#define NBLK  128                 // persistent-kernel grid (32 blocks per batch)

#define SWZ(j) ((j) + ((j) >> 4))   // bank-conflict swizzle for window rp smem

// ---------------- device scratch ----------------
__device__ float    g_dn[A * KA];
__device__ float    g_rp[B * RPS];
__device__ float    g_recon[B * RPS];
__device__ float    g_fm[(size_t)B * A * FMS];
__device__ u64      g_cmax[B * A * NCH];
__device__ u64      g_gbest[B];
__device__ int      g_sel_pos[B];
__device__ unsigned g_arrive;

// ---------------- helpers ----------------
__device__ __forceinline__ u64 packkey(float v, unsigned flat) {
    unsigned u = __float_as_uint(v);
    u = (u & 0x80000000u) ? ~u : (u | 0x80000000u);     // orderable float
    return ((u64)u << 32) | (unsigned)(~flat);          // ties -> smallest flat
}
__device__ __forceinline__ u64 pack2(float lo, float hi) {
    u64 r;
    asm("mov.b64 %0, {%1, %2};" : "=l"(r) : "f"(lo), "f"(hi));
    return r;
}
__device__ __forceinline__ void unpack2(u64 v, float& lo, float& hi) {
    asm("mov.b64 {%0, %1}, %2;" : "=f"(lo), "=f"(hi) : "l"(v));
}
__device__ __forceinline__ void ffma2(u64& acc, u64 a, u64 b) {
    asm("fma.rn.f32x2 %0, %1, %2, %0;" : "+l"(acc) : "l"(a), "l"(b));
}
__device__ __forceinline__ u64 umax(u64 a, u64 b) { return a > b ? a : b; }

// software grid barrier: all NBLK blocks resident (128 < 148 SMs)
__device__ __forceinline__ void gridbar(unsigned target) {
    __syncthreads();
    if (threadIdx.x == 0) {
        __threadfence();
        atomicAdd(&g_arrive, 1u);
        while (*((volatile unsigned*)&g_arrive) < target) { }
        __threadfence();
    }
    __syncthreads();
}

// ---------------- setup kernels ----------------
__global__ void normd_kernel(const float* __restrict__ d) {
    const int a = blockIdx.x;
    const float v = d[a * KA + threadIdx.x];
    float ss = v * v;
    #pragma unroll
    for (int o = 16; o; o >>= 1) ss += __shfl_down_sync(0xffffffffu, ss, o);
    __shared__ float s[8];
    __shared__ float norm;
    if ((threadIdx.x & 31) == 0) s[threadIdx.x >> 5] = ss;
    __syncthreads();
    if (threadIdx.x == 0) {
        float tot = 0.f;
        #pragma unroll
        for (int i = 0; i < 8; i++) tot += s[i];
        norm = sqrtf(tot) + 1e-12f;
    }
    __syncthreads();
    g_dn[a * KA + threadIdx.x] = v / norm;
}

__global__ void init_kernel(const float* __restrict__ x) {
    const int idx = blockIdx.x * blockDim.x + threadIdx.x;
    if (idx == 0) g_arrive = 0u;
    if (idx < B) g_gbest[idx] = 0ull;
    if (idx < B * A * NCH) g_cmax[idx] = 0ull;
    if (idx >= B * RPS) return;
    const int b = idx / RPS, t = idx - b * RPS;
    float v = 0.f;
    if (t >= PAD && t < PAD + T) v = x[b * T + (t - PAD)];
    g_rp[idx] = v;
    g_recon[idx] = 0.f;
}

// ---------------- full correlation (+ fused chunk max) ----------------
__global__ void __launch_bounds__(256) conv_full_kernel() {
    const int b = blockIdx.z;
    const int tbase = blockIdx.x * 128;
    const int a0 = blockIdx.y * 64;
    const int tid = threadIdx.x;
    const int w = tid >> 5, l = tid & 31;

    __shared__ float s_dnf[128][66];
    __shared__ u64   s_rp2[384];
    __shared__ u64   s_red[64];

    const float* __restrict__ rp = g_rp + b * RPS;

    if (tid < 64) s_red[tid] = 0ull;
    for (int j = tid; j < 384; j += 256) {
        const float r = rp[tbase + j];
        s_rp2[j] = pack2(r, r);
    }

    u64 acc2[16], rbuf[16];
    #pragma unroll
    for (int i = 0; i < 16; i++) acc2[i] = 0ull;

    const int tw = w * 16;

    #pragma unroll 1
    for (int kc = 0; kc < 256; kc += 128) {
        __syncthreads();
        for (int i = tid; i < 64 * 128; i += 256) {
            const int k = i & 127, aa = i >> 7;
            s_dnf[k][aa] = g_dn[(a0 + aa) * KA + kc + k];
        }
        __syncthreads();
        if (kc == 0) {
            #pragma unroll
            for (int j = 0; j < 16; j++) rbuf[j] = s_rp2[tw + j];
        }
        #pragma unroll 1
        for (int k8 = 0; k8 < 128; k8 += 16) {
            #pragma unroll
            for (int kk = 0; kk < 16; kk++) {
                const u64 dp = *reinterpret_cast<const u64*>(&s_dnf[k8 + kk][2 * l]);
                #pragma unroll
                for (int i = 0; i < 16; i++)
                    ffma2(acc2[i], rbuf[(i + kk) & 15], dp);
                rbuf[kk] = s_rp2[tw + kc + k8 + kk + 16];
            }
        }
    }

    float vlo[16], vhi[16];
    #pragma unroll
    for (int i = 0; i < 16; i++) unpack2(acc2[i], vlo[i], vhi[i]);

    const int alo = a0 + 2 * l;
    float* __restrict__ rowlo = g_fm + (size_t)(b * A + alo) * FMS;
    float* __restrict__ rowhi = rowlo + FMS;
    const int t0 = tbase + tw;

    if (tbase + 128 <= TOUT) {
        #pragma unroll
        for (int q = 0; q < 4; q++) {
            float4 wl = make_float4(vlo[4*q], vlo[4*q+1], vlo[4*q+2], vlo[4*q+3]);
            float4 wh = make_float4(vhi[4*q], vhi[4*q+1], vhi[4*q+2], vhi[4*q+3]);
            *reinterpret_cast<float4*>(&rowlo[t0 + 4*q]) = wl;
            *reinterpret_cast<float4*>(&rowhi[t0 + 4*q]) = wh;
        }
    } else {
        #pragma unroll
        for (int i = 0; i < 16; i++) {
            const int t = t0 + i;
            if (t < TOUT) { rowlo[t] = vlo[i]; rowhi[t] = vhi[i]; }
        }
    }

    u64 klo = 0ull, khi = 0ull;
    #pragma unroll
    for (int i = 0; i < 16; i++) {
        const int t = t0 + i;
        if (t < TOUT) {
            klo = umax(klo, packkey(vlo[i], (unsigned)(alo * TOUT + t)));
            khi = umax(khi, packkey(vhi[i], (unsigned)((alo + 1) * TOUT + t)));
        }
    }
    atomicMax(&s_red[2 * l],     klo);
    atomicMax(&s_red[2 * l + 1], khi);
    __syncthreads();
    if (tid < 64) {
        const int c = tbase >> 9;
        atomicMax(&g_cmax[(b * A + a0 + tid) * NCH + c], s_red[tid]);
    }
}

// ---------------- persistent iteration kernel ----------------
// 128 blocks x 256 threads, all resident. Block blk: batch b = blk>>5,
// atom group a0 = (blk&31)*8. Phase 0: atom max -> g_gbest. Then 16 iterations:
//   bar; leader block of each batch decodes gbest + updates rp/recon; bar;
//   window conv over this block's 8 atoms + chunk rebuild + atomicMax gbest.
__global__ void __launch_bounds__(256) persist_kernel() {
    const int blk = blockIdx.x;
    const int b = blk >> 5;
    const int a0 = (blk & 31) * 8;
    const int tid = threadIdx.x;
    const int w = tid >> 5, l = tid & 31;

    __shared__ u64 s_rp2[832];
    __shared__ u64 s_dn2[256 * 4];
    __shared__ int sh_a, sh_p;
    __shared__ float sh_v;

    // phase 0a: stage this block's 8 atoms once (dictionary is loop-invariant)
    for (int i = tid; i < 1024; i += 256) {
        const int k = i & 255, p = i >> 8;
        s_dn2[k * 4 + p] = pack2(g_dn[(a0 + 2 * p) * KA + k],
                                 g_dn[(a0 + 2 * p + 1) * KA + k]);
    }

    // phase 0b: atom max over initial chunk maxima (8 rows per block, warp/row)
    {
        const int row = blk * 8 + w;                 // = b*A + atom
        const u64* __restrict__ cm = g_cmax + row * NCH;
        u64 v = cm[l];
        if (l == 0) v = umax(v, cm[32]);
        #pragma unroll
        for (int o = 16; o; o >>= 1) v = umax(v, __shfl_xor_sync(0xffffffffu, v, o));
        if (l == 0) atomicMax(&g_gbest[b], v);
    }

    unsigned target = 0;
    const bool leader = (blk & 31) == 0;

    for (int it = 0; it < NITER; ++it) {
        target += NBLK;
        gridbar(target);                             // gbest complete

        if (leader) {
            if (tid == 0) {
                const u64 best = g_gbest[b];
                const unsigned hiw = (unsigned)(best >> 32);
                const unsigned u = (hiw & 0x80000000u) ? (hiw & 0x7fffffffu) : ~hiw;
                const unsigned flat = ~(unsigned)(best & 0xffffffffu);
                sh_a = flat / TOUT;
                sh_p = flat % TOUT;
                sh_v = __uint_as_float(u);
                g_sel_pos[b] = sh_p;
                g_gbest[b] = 0ull;
            }
            __syncthreads();
            const float xv = sh_v * g_dn[sh_a * KA + tid];
            g_rp[b * RPS + sh_p + tid]    -= xv;
            g_recon[b * RPS + sh_p + tid] += xv;
        }

        target += NBLK;
        gridbar(target);                             // rp updated, gbest reset

        if (it == NITER - 1) break;

        // ---- window re-correlation for 8 atoms ----
        const int pos = g_sel_pos[b];
        const int lo = max(0, pos - (KA - 1));
        const int hi = min(TOUT - 1, pos + (KA - 1));

        const float* __restrict__ rp = g_rp + b * RPS;
        for (int j = tid; j < 776; j += 256) {
            const float r = rp[lo + j];              // zero tail keeps this in-bounds
            s_rp2[SWZ(j)] = pack2(r, r);
        }
        __syncthreads();

        const int p = w & 3, h = w >> 2;
        const int t0 = h * 256 + l * 8;

        u64 acc2[8], rbuf[8];
        #pragma unroll
        for (int i = 0; i < 8; i++) acc2[i] = 0ull;
        #pragma unroll
        for (int j = 0; j < 8; j++) rbuf[j] = s_rp2[SWZ(t0 + j)];

        #pragma unroll 1
        for (int k8 = 0; k8 < 256; k8 += 8) {
            #pragma unroll
            for (int kk = 0; kk < 8; kk++) {
                const u64 dp = s_dn2[(k8 + kk) * 4 + p];
                #pragma unroll
                for (int i = 0; i < 8; i++)
                    ffma2(acc2[i], rbuf[(i + kk) & 7], dp);
                rbuf[kk] = s_rp2[SWZ(t0 + k8 + kk + 8)];
            }
        }

        float vlo[8], vhi[8];
        #pragma unroll
        for (int i = 0; i < 8; i++) unpack2(acc2[i], vlo[i], vhi[i]);

        const int alo = a0 + 2 * p;
        float* __restrict__ rowlo = g_fm + (size_t)(b * A + alo) * FMS;
        float* __restrict__ rowhi = rowlo + FMS;
        #pragma unroll
        for (int i = 0; i < 8; i++) {
            const int t = lo + t0 + i;
            if (t <= hi) { rowlo[t] = vlo[i]; rowhi[t] = vhi[i]; }
        }
        __syncthreads();                             // fm visible block-wide

        // rebuild 1-2 chunks for atom a0+w, then atom max + global best
        const int aw = a0 + w;
        const int c0 = lo >> 9, c1 = hi >> 9;
        const int tstart = c0 << 9;
        const int tend = min((c1 + 1) << 9, TOUT);
        const float* __restrict__ rowa = g_fm + (size_t)(b * A + aw) * FMS;

        u64 b0 = 0ull, b1 = 0ull;
        for (int t = tstart + l; t < tend; t += 32) {
            const u64 key = packkey(rowa[t], (unsigned)(aw * TOUT + t));
            if ((t >> 9) == c0) b0 = umax(b0, key); else b1 = umax(b1, key);
        }
        #pragma unroll
        for (int o = 16; o; o >>= 1) {
            b0 = umax(b0, __shfl_xor_sync(0xffffffffu, b0, o));
            b1 = umax(b1, __shfl_xor_sync(0xffffffffu, b1, o));
        }
        u64* cmrow = g_cmax + (b * A + aw) * NCH;
        if (l == 0) {
            cmrow[c0] = b0;
            if (c1 != c0) cmrow[c1] = b1;
        }
        u64 v = (l == c0) ? b0 : ((l == c1) ? b1 : cmrow[l]);
        if (l == 0) {
            const u64 v2 = (32 == c0) ? b0 : ((32 == c1) ? b1 : cmrow[32]);
            v = umax(v, v2);
        }
        #pragma unroll
        for (int o = 16; o; o >>= 1) v = umax(v, __shfl_xor_sync(0xffffffffu, v, o));
        if (l == 0) atomicMax(&g_gbest[b], v);
    }
}

// crop padded recon to output
__global__ void out_kernel(float* __restrict__ out) {
    const int idx = blockIdx.x * blockDim.x + threadIdx.x;
    if (idx >= B * T) return;
    const int b = idx / T, t = idx - b * T;
    out[idx] = g_recon[b * RPS + PAD + t];
}

// ---------------- launch ----------------
extern "C" void kernel_launch(void* const* d_in, const int* in_sizes, int n_in,
                              void* d_out, int out_size) {
    const float* x = (const float*)d_in[0];
    const float* d = (const float*)d_in[1];
    float* out = (float*)d_out;
    (void)in_sizes; (void)n_in; (void)out_size;

    normd_kernel<<<A, KA>>>(d);
    init_kernel<<<(B * RPS + 255) / 256, 256>>>(x);

    conv_full_kernel<<<dim3(129, 4, B), 256>>>();
    persist_kernel<<<NBLK, 256>>>();

    out_kernel<<<(B * T + 255) / 256, 256>>>(out);
}